// round 10
// baseline (speedup 1.0000x reference)
#include <cuda_runtime.h>
#include <stdint.h>

// EmbeddingDropout: out[r, :] = weight[x[r], :] * mask[x[r]]
// x: [16384] int32 token ids, weight: [50257, 512] f32, mask: [50257] f32.
// Output: [16384, 512] f32.
//
// FINAL — converged after 8 structural experiments:
//   - one warp per row; each thread moves 4 independent float4 (LDG.128),
//     fully coalesced 512 B quanta per warp-step
//   - __ldg on weight/mask (read-only L1 path; dup-token L2 reuse)
//   - __stcs streaming stores (evict-first) for the write-once 32 MB output
// Measured invariances: timed duration flat (10.69-10.75 us) across per-warp
// MLP 1/4/8, wave count 1/2, and store mechanism; v8.256 loads (+/- L2
// policy) and TMA bulk stores regress. Bottleneck: DRAM efficiency on
// randomly-located 2 KB row reads (~33% of peak) — a memory-system floor,
// not an SM-side limit (all pipes <35%, issue <10%).

#define D 512
#define D4 (D / 4)            // 128 float4 per row
#define THREADS 256           // 8 warps -> 8 rows per block
#define ROWS_PER_BLOCK (THREADS / 32)

__global__ __launch_bounds__(THREADS) void embedding_dropout_kernel(
    const int* __restrict__ x,           // [N]
    const float4* __restrict__ weight,   // [V, D4]
    const float* __restrict__ mask,      // [V]
    float4* __restrict__ out,            // [N, D4]
    int n_rows)
{
    int row  = (blockIdx.x * THREADS + threadIdx.x) >> 5;  // one warp per row
    int lane = threadIdx.x & 31;
    if (row >= n_rows) return;

    int idx = __ldg(&x[row]);            // L1 broadcast across the warp
    float s = __ldg(&mask[idx]);

    const float4* wrow = weight + (size_t)idx * D4;
    float4*       orow = out    + (size_t)row * D4;

    float4 v[4];
    #pragma unroll
    for (int i = 0; i < 4; i++)          // 4 independent 512B-coalesced loads
        v[i] = __ldg(&wrow[lane + 32 * i]);

    #pragma unroll
    for (int i = 0; i < 4; i++) {
        v[i].x *= s; v[i].y *= s; v[i].z *= s; v[i].w *= s;
        __stcs(&orow[lane + 32 * i], v[i]);   // streaming: evict-first in L2
    }
}

extern "C" void kernel_launch(void* const* d_in, const int* in_sizes, int n_in,
                              void* d_out, int out_size)
{
    // Identify inputs by element count: x=16384, weight=25731584, mask=50257.
    long long max_sz = -1, mid_sz = -1;
    int wi = -1, mi = -1, xi = -1;
    for (int i = 0; i < n_in; i++)
        if (in_sizes[i] > max_sz) { max_sz = in_sizes[i]; wi = i; }
    for (int i = 0; i < n_in; i++)
        if (i != wi && in_sizes[i] > mid_sz) { mid_sz = in_sizes[i]; mi = i; }
    for (int i = 0; i < n_in; i++)
        if (i != wi && i != mi) { xi = i; break; }

    const int*    x    = (const int*)d_in[xi];
    const float4* w    = (const float4*)d_in[wi];
    const float*  mask = (const float*)d_in[mi];
    float4*       out  = (float4*)d_out;
    int n_rows = in_sizes[xi];

    int blocks = (n_rows + ROWS_PER_BLOCK - 1) / ROWS_PER_BLOCK;
    embedding_dropout_kernel<<<blocks, THREADS>>>(x, w, mask, out, n_rows);
}